// round 17
// baseline (speedup 1.0000x reference)
#include <cuda_runtime.h>
#include <cuda_bf16.h>
#include <math.h>
#include <stdint.h>

// ----------------------------------------------------------------------------
// DiT block. Round 17 (= round 16 resubmit after infra flake):
// GEMM CTA tile 256x128 (4Mx2N warps, 64x64 warp tile, 1 CTA/SM) to cut L2
// traffic 25% — testing the L2-bound hypothesis. Everything else identical
// to round 15. bf16 storage, fp32 math.
// Shapes: B=4, N=1024, H=1024, NH=16, DH=64, MLP=4096. Rows = B*N = 4096.
// ----------------------------------------------------------------------------

#define RWS 4096
#define HID 1024
#define MLPD 4096

// ---------------- scratch (device globals; no allocations allowed) ----------
__device__ float g_s_cond[1024];
__device__ float g_s_qkv[1024];
__device__ float g_s_out[1024];
__device__ float g_s_mlp1[1024];
__device__ float g_s_mlp2[4096];
__device__ float g_ccp[32 * 8192];
__device__ float g_cc[4 * 2048];
__device__ __nv_bfloat16 g_xs[RWS * HID];
__device__ __nv_bfloat16 g_big[RWS * MLPD];
__device__ __nv_bfloat16 g_q[64 * 1024 * 64];
__device__ __nv_bfloat16 g_k[64 * 1024 * 64];
__device__ __nv_bfloat16 g_v[64 * 1024 * 64];
__device__ __nv_bfloat16 g_xattn[RWS * HID];
__device__ __nv_bfloat16 g_t1[RWS * HID];
__device__ float g_x1[RWS * HID];
__device__ __nv_bfloat16 g_wt_qkv[3072 * 1024];
__device__ __nv_bfloat16 g_wt_out[1024 * 1024];
__device__ __nv_bfloat16 g_wt_mlp1[4096 * 1024];
__device__ __nv_bfloat16 g_wt_mlp2[1024 * 4096];

// ---------------- small helpers ----------------------------------------------
__device__ __forceinline__ uint32_t s2u(const void* p) {
    uint32_t a;
    asm("{ .reg .u64 t; cvta.to.shared.u64 t, %1; cvt.u32.u64 %0, t; }"
        : "=r"(a) : "l"(p));
    return a;
}
__device__ __forceinline__ uint32_t packbf(float lo, float hi) {
    uint32_t r;
    asm("cvt.rn.bf16x2.f32 %0, %1, %2;" : "=r"(r) : "f"(hi), "f"(lo));
    return r;
}
__device__ __forceinline__ float2 upk(uint32_t u) {
    __nv_bfloat162 h = *reinterpret_cast<__nv_bfloat162*>(&u);
    return __bfloat1622float2(h);
}
__device__ __forceinline__ void cpa16(uint32_t saddr, const void* g) {
    asm volatile("cp.async.cg.shared.global [%0], [%1], 16;"
                 :: "r"(saddr), "l"(g) : "memory");
}
#define CPA_COMMIT() asm volatile("cp.async.commit_group;" ::: "memory")
#define CPA_WAIT(n)  asm volatile("cp.async.wait_group %0;" :: "n"(n) : "memory")
__device__ __forceinline__ void ldsm4(uint32_t* r, uint32_t a) {
    asm volatile("ldmatrix.sync.aligned.m8n8.x4.shared.b16 {%0,%1,%2,%3}, [%4];"
                 : "=r"(r[0]), "=r"(r[1]), "=r"(r[2]), "=r"(r[3]) : "r"(a));
}
__device__ __forceinline__ void ldsm2(uint32_t* r, uint32_t a) {
    asm volatile("ldmatrix.sync.aligned.m8n8.x2.shared.b16 {%0,%1}, [%2];"
                 : "=r"(r[0]), "=r"(r[1]) : "r"(a));
}
__device__ __forceinline__ void ldsm2t(uint32_t* r, uint32_t a) {
    asm volatile("ldmatrix.sync.aligned.m8n8.x2.trans.shared.b16 {%0,%1}, [%2];"
                 : "=r"(r[0]), "=r"(r[1]) : "r"(a));
}
__device__ __forceinline__ void mma16(float* c, const uint32_t* a, const uint32_t* b) {
    asm volatile("mma.sync.aligned.m16n8k16.row.col.f32.bf16.bf16.f32 "
                 "{%0,%1,%2,%3}, {%4,%5,%6,%7}, {%8,%9}, {%0,%1,%2,%3};"
                 : "+f"(c[0]), "+f"(c[1]), "+f"(c[2]), "+f"(c[3])
                 : "r"(a[0]), "r"(a[1]), "r"(a[2]), "r"(a[3]),
                   "r"(b[0]), "r"(b[1]));
}
// exp(x) for |x| <= 0.125: degree-3 Taylor, abs err <= x^4/24 ~ 1.1e-5
__device__ __forceinline__ float exps(float x) {
    return 1.f + x * (1.f + x * (0.5f + x * (1.f / 6.f)));
}

// ---------------- block reduce ------------------------------------------------
__device__ __forceinline__ float blockReduceSum(float v) {
    __shared__ float sh[9];
    int lane = threadIdx.x & 31, wid = threadIdx.x >> 5;
#pragma unroll
    for (int m = 16; m; m >>= 1) v += __shfl_xor_sync(0xffffffffu, v, m);
    if (lane == 0) sh[wid] = v;
    __syncthreads();
    if (wid == 0) {
        float r = (lane < (int)(blockDim.x >> 5)) ? sh[lane] : 0.f;
#pragma unroll
        for (int m = 4; m; m >>= 1) r += __shfl_xor_sync(0xffffffffu, r, m);
        if (lane == 0) sh[8] = r;
    }
    __syncthreads();
    return sh[8];
}

// ---------------- fused rownorm: all 5 weights, warp per row ------------------
__global__ void rownorm_all_kernel(const float* __restrict__ w_cond,
                                   const float* __restrict__ w_qkv,
                                   const float* __restrict__ w_out,
                                   const float* __restrict__ w_mlp1,
                                   const float* __restrict__ w_mlp2,
                                   float* __restrict__ s_cond,
                                   float* __restrict__ s_qkv,
                                   float* __restrict__ s_out,
                                   float* __restrict__ s_mlp1,
                                   float* __restrict__ s_mlp2) {
    int gw = blockIdx.x * 8 + (threadIdx.x >> 5);
    int lane = threadIdx.x & 31;
    const float* w;
    float* s;
    int row, cols, rows;
    if (gw < 1024)      { w = w_cond; s = s_cond; row = gw;        cols = 2048; rows = 1024; }
    else if (gw < 2048) { w = w_qkv;  s = s_qkv;  row = gw - 1024; cols = 3072; rows = 1024; }
    else if (gw < 3072) { w = w_out;  s = s_out;  row = gw - 2048; cols = 1024; rows = 1024; }
    else if (gw < 4096) { w = w_mlp1; s = s_mlp1; row = gw - 3072; cols = 4096; rows = 1024; }
    else                { w = w_mlp2; s = s_mlp2; row = gw - 4096; cols = 1024; rows = 4096; }
    const float4* p = (const float4*)(w + (size_t)row * cols);
    int n4 = cols >> 2;
    float sum = 0.f;
    for (int i = lane; i < n4; i += 32) {
        float4 v = p[i];
        sum += v.x * v.x + v.y * v.y + v.z * v.z + v.w * v.w;
    }
#pragma unroll
    for (int m = 16; m; m >>= 1) sum += __shfl_xor_sync(0xffffffffu, sum, m);
    if (lane == 0)
        s[row] = 1.0f / ((sqrtf(sum) * sqrtf((float)cols) + 1e-4f) * sqrtf((float)rows));
}

// ---------------- fused transpose (all 4 weights), paired bf16 stores --------
__global__ void transpose_all_kernel(const float* __restrict__ w_qkv,
                                     const float* __restrict__ w_out,
                                     const float* __restrict__ w_mlp1,
                                     const float* __restrict__ w_mlp2,
                                     const float* __restrict__ s_qkv,
                                     const float* __restrict__ s_out,
                                     const float* __restrict__ s_mlp1,
                                     const float* __restrict__ s_mlp2,
                                     __nv_bfloat16* __restrict__ wt_qkv,
                                     __nv_bfloat16* __restrict__ wt_out,
                                     __nv_bfloat16* __restrict__ wt_mlp1,
                                     __nv_bfloat16* __restrict__ wt_mlp2) {
    __shared__ float t[32][33];
    int bid = blockIdx.x;
    const float* W;
    const float* s;
    __nv_bfloat16* Wt;
    int K, N, bx, by;
    if (bid < 3072)       { W = w_qkv;  s = s_qkv;  Wt = wt_qkv;  K = 1024; N = 3072;
                            bx = bid % 96;  by = bid / 96; }
    else if (bid < 4096)  { int r = bid - 3072; W = w_out;  s = s_out;  Wt = wt_out;
                            K = 1024; N = 1024; bx = r % 32; by = r / 32; }
    else if (bid < 8192)  { int r = bid - 4096; W = w_mlp1; s = s_mlp1; Wt = wt_mlp1;
                            K = 1024; N = 4096; bx = r % 128; by = r / 128; }
    else                  { int r = bid - 8192; W = w_mlp2; s = s_mlp2; Wt = wt_mlp2;
                            K = 4096; N = 1024; bx = r % 32; by = r / 32; }
    int tx = threadIdx.x, ty = threadIdx.y;
    int tid = ty * 32 + tx;
    int n = bx * 32 + tx;
#pragma unroll
    for (int i = 0; i < 4; i++) {
        int k = by * 32 + ty + i * 8;
        t[ty + i * 8][tx] = W[(size_t)k * N + n] * s[k];
    }
    __syncthreads();
    int n0 = bx * 32, k0 = by * 32;
#pragma unroll
    for (int ss = 0; ss < 2; ss++) {
        int pi = tid + ss * 256;
        int nl = pi >> 4, kp = pi & 15;
        uint32_t val = packbf(t[2 * kp][nl], t[2 * kp + 1][nl]);
        *(uint32_t*)&Wt[(size_t)(n0 + nl) * K + k0 + 2 * kp] = val;
    }
}

// ---------------- cond path: split-K partial with inline mp_silu --------------
__global__ void cond_gemm_part_kernel(const float* __restrict__ c,
                                      const float* __restrict__ s_cond,
                                      const float* __restrict__ w,
                                      float* __restrict__ ccp) {
    __shared__ float sh[4][32];
    int k0 = blockIdx.y * 32;
    int j = blockIdx.x * 256 + threadIdx.x;
    if (threadIdx.x < 128) {
        int r = threadIdx.x >> 5, kk = threadIdx.x & 31;
        float v = c[r * 1024 + k0 + kk];
        float sv = v / (1.f + __expf(-v));
        sh[r][kk] = sv * (1.0f / 0.596f) * s_cond[k0 + kk];
    }
    __syncthreads();
    float a0 = 0.f, a1 = 0.f, a2 = 0.f, a3 = 0.f;
#pragma unroll
    for (int kk = 0; kk < 32; kk++) {
        float wv = w[(size_t)(k0 + kk) * 2048 + j];
        a0 += sh[0][kk] * wv; a1 += sh[1][kk] * wv;
        a2 += sh[2][kk] * wv; a3 += sh[3][kk] * wv;
    }
    float* dst = ccp + (size_t)blockIdx.y * 8192;
    dst[j] = a0; dst[2048 + j] = a1; dst[4096 + j] = a2; dst[6144 + j] = a3;
}

__global__ void cond_reduce_kernel(const float* __restrict__ ccp,
                                   float* __restrict__ cc) {
    int i = blockIdx.x * 256 + threadIdx.x;
    float s = 0.f;
#pragma unroll
    for (int p = 0; p < 32; p++) s += ccp[(size_t)p * 8192 + i];
    cc[i] = s;
}

// ---------------- x conditioning -> bf16 xs ----------------------------------
__global__ void xcond_kernel(const float* __restrict__ xin, const float* __restrict__ cc,
                             __nv_bfloat16* __restrict__ xs) {
    int row = blockIdx.x;
    int b = row >> 10;
    float4 v = ((const float4*)(xin + (size_t)row * HID))[threadIdx.x];
    float sum = v.x * v.x + v.y * v.y + v.z * v.z + v.w * v.w;
    float tot = blockReduceSum(sum);
    float r = rsqrtf(tot * (1.f / 1024.f) + 1e-4f);
    int col = threadIdx.x * 4;
    const float* ccb = cc + b * 2048;
    float ox = v.x * r * (1.f + ccb[col + 0]) + ccb[1024 + col + 0];
    float oy = v.y * r * (1.f + ccb[col + 1]) + ccb[1024 + col + 1];
    float oz = v.z * r * (1.f + ccb[col + 2]) + ccb[1024 + col + 2];
    float ow = v.w * r * (1.f + ccb[col + 3]) + ccb[1024 + col + 3];
    uint2 o = make_uint2(packbf(ox, oy), packbf(oz, ow));
    *(uint2*)&xs[(size_t)row * HID + col] = o;
}

// ---------------- bf16 mma GEMM, CTA 256x128, 3-stage cp.async ---------------
// 8 warps (4M x 2N), warp tile 64x64. smem/stage: A 32K + B 16K = 48K.
// B fragments via ldsm.x4 pairs (lanes 16-31 offset +8 rows).
#define GEMM_SMEM (3 * 49152)

__global__ __launch_bounds__(256)
void gemm_mma_kernel(const __nv_bfloat16* __restrict__ A,
                     const __nv_bfloat16* __restrict__ Bt,
                     __nv_bfloat16* __restrict__ C, int K, int N) {
    extern __shared__ char smem[];
    uint32_t sb = s2u(smem);
    int tid = threadIdx.x, lane = tid & 31, wid = tid >> 5;
    int wm = wid & 3, wn = wid >> 2;           // 4 M-warps x 2 N-warps
    int m0 = blockIdx.y << 8, n0 = blockIdx.x << 7;
    const __nv_bfloat16* Ab = A + (size_t)m0 * K;
    const __nv_bfloat16* Bb = Bt + (size_t)n0 * K;

    // A: 2048 slots (256 rows x 8 groups) -> 8 per thread; B: 1024 -> 4.
    int arow[8], ag[8];
    uint32_t aswo[8];
#pragma unroll
    for (int i = 0; i < 8; i++) {
        int idx = tid + i * 256;
        arow[i] = idx >> 3;
        ag[i] = idx & 7;
        aswo[i] = (uint32_t)(arow[i] * 128 + ((ag[i] ^ (arow[i] & 7)) << 4));
    }
    int brow[4], bg[4];
    uint32_t bswo[4];
#pragma unroll
    for (int i = 0; i < 4; i++) {
        int idx = tid + i * 256;
        brow[i] = idx >> 3;
        bg[i] = idx & 7;
        bswo[i] = (uint32_t)(brow[i] * 128 + ((bg[i] ^ (brow[i] & 7)) << 4));
    }

    uint32_t rowA = (uint32_t)((wm << 6) + (lane & 15));
    uint32_t aOff = rowA * 128, aXor = rowA & 7, aG = (uint32_t)(lane >> 4);
    uint32_t rowB = (uint32_t)((wn << 6) + (lane & 7) + ((lane >> 4) << 3));
    uint32_t bOff = rowB * 128, bXor = (uint32_t)(lane & 7);
    uint32_t bG = (uint32_t)((lane >> 3) & 1);

    float acc[4][8][4];
#pragma unroll
    for (int i = 0; i < 4; i++)
#pragma unroll
        for (int j = 0; j < 8; j++)
#pragma unroll
            for (int l = 0; l < 4; l++) acc[i][j][l] = 0.f;

    int nct = K >> 6;

    auto load = [&](int kt) {
        if (kt < nct) {
            int buf = kt % 3;
            uint32_t ta = sb + (uint32_t)buf * 49152, tb = ta + 32768;
            const __nv_bfloat16* Ap = Ab + kt * 64;
            const __nv_bfloat16* Bp = Bb + kt * 64;
#pragma unroll
            for (int i = 0; i < 8; i++)
                cpa16(ta + aswo[i], Ap + (size_t)arow[i] * K + ag[i] * 8);
#pragma unroll
            for (int i = 0; i < 4; i++)
                cpa16(tb + bswo[i], Bp + (size_t)brow[i] * K + bg[i] * 8);
        }
        CPA_COMMIT();
    };
    auto compute = [&](int buf) {
        uint32_t aB = sb + (uint32_t)buf * 49152 + aOff;
        uint32_t bB = sb + (uint32_t)buf * 49152 + 32768 + bOff;
#pragma unroll
        for (int ks = 0; ks < 4; ks++) {
            uint32_t a[4][4], b[8][2];
#pragma unroll
            for (int mt = 0; mt < 4; mt++)
                ldsm4(a[mt], aB + mt * 2048 + ((((uint32_t)(2 * ks) + aG) ^ aXor) << 4));
#pragma unroll
            for (int p = 0; p < 4; p++) {
                uint32_t bq[4];
                ldsm4(bq, bB + p * 2048 + ((((uint32_t)(2 * ks) + bG) ^ bXor) << 4));
                b[2 * p][0] = bq[0]; b[2 * p][1] = bq[1];
                b[2 * p + 1][0] = bq[2]; b[2 * p + 1][1] = bq[3];
            }
#pragma unroll
            for (int mt = 0; mt < 4; mt++)
#pragma unroll
                for (int nt = 0; nt < 8; nt++)
                    mma16(acc[mt][nt], a[mt], b[nt]);
        }
    };

    load(0);
    load(1);
    for (int kt = 0; kt < nct; kt++) {
        CPA_WAIT(1);
        __syncthreads();
        load(kt + 2);
        compute(kt % 3);
    }

    int crow = m0 + (wm << 6) + (lane >> 2);
    int ccol = n0 + (wn << 6) + ((lane & 3) << 1);
#pragma unroll
    for (int mt = 0; mt < 4; mt++)
#pragma unroll
        for (int nt = 0; nt < 8; nt++) {
            *(uint32_t*)&C[(size_t)(crow + mt * 16) * N + ccol + nt * 8] =
                packbf(acc[mt][nt][0], acc[mt][nt][1]);
            *(uint32_t*)&C[(size_t)(crow + mt * 16 + 8) * N + ccol + nt * 8] =
                packbf(acc[mt][nt][2], acc[mt][nt][3]);
        }
}

// ---------------- qkv post: norms + head layout, bf16 in/out -----------------
__global__ void qkv_post_kernel(const __nv_bfloat16* __restrict__ qkv,
                                __nv_bfloat16* __restrict__ q,
                                __nv_bfloat16* __restrict__ k,
                                __nv_bfloat16* __restrict__ v) {
    int row = blockIdx.x;
    int seg = blockIdx.y;
    int b = row >> 10, n = row & 1023;
    uint2 u = *(const uint2*)&qkv[(size_t)row * 3072 + seg * 1024 + threadIdx.x * 4];
    float2 v0 = upk(u.x), v1 = upk(u.y);
    float ls = v0.x * v0.x + v0.y * v0.y + v1.x * v1.x + v1.y * v1.y;
    float hs = ls;
#pragma unroll
    for (int m = 8; m; m >>= 1) hs += __shfl_xor_sync(0xffffffffu, hs, m, 16);
    float tot = blockReduceSum(ls);
    float r = rsqrtf(tot * (1.f / 1024.f) + 1e-4f);
    float scale = (seg < 2) ? r * rsqrtf(r * r * hs + 1e-6f) : r;
    if (seg == 0) scale *= 0.125f;
    int e = threadIdx.x * 4;
    int h = e >> 6, d = e & 63;
    __nv_bfloat16* dst = (seg == 0) ? q : ((seg == 1) ? k : v);
    uint32_t p0 = packbf(v0.x * scale, v0.y * scale);
    uint32_t p1 = packbf(v1.x * scale, v1.y * scale);
    *(uint2*)&dst[(((size_t)(b * 16 + h)) * 1024 + n) * 64 + d] = make_uint2(p0, p1);
}

// ---------------- attention: 4 warps x 32 q-rows, 2-stage cp.async KV --------
__global__ __launch_bounds__(128)
void attn_mma_kernel(const __nv_bfloat16* __restrict__ q,
                     const __nv_bfloat16* __restrict__ k,
                     const __nv_bfloat16* __restrict__ v,
                     __nv_bfloat16* __restrict__ xattn) {
    __shared__ __align__(16) char Qs[16384];
    __shared__ __align__(16) char Ks[2][8192];
    __shared__ __align__(16) char Vs[2][8192];
    uint32_t qsb = s2u(Qs);
    uint32_t ksb[2] = {s2u(Ks[0]), s2u(Ks[1])};
    uint32_t vsb[2] = {s2u(Vs[0]), s2u(Vs[1])};
    int tid = threadIdx.x, lane = tid & 31, w = tid >> 5;
    int bh = blockIdx.y;
    int b = bh >> 4, h = bh & 15;
    int q0 = blockIdx.x << 7;
    const __nv_bfloat16* qh = q + (size_t)bh * (1024 * 64);
    const __nv_bfloat16* kh = k + (size_t)bh * (1024 * 64);
    const __nv_bfloat16* vh = v + (size_t)bh * (1024 * 64);

    int kvrow[4], kvg[4];
    uint32_t kvswo[4];
#pragma unroll
    for (int i = 0; i < 4; i++) {
        int idx = tid + i * 128;
        kvrow[i] = idx >> 3;
        kvg[i] = idx & 7;
        kvswo[i] = (uint32_t)(kvrow[i] * 128 + ((kvg[i] ^ (kvrow[i] & 7)) << 4));
    }
    auto load_kv = [&](int kt) {
        if (kt < 16) {
            int buf = kt & 1;
            const __nv_bfloat16* kp = kh + (size_t)kt * 64 * 64;
            const __nv_bfloat16* vp = vh + (size_t)kt * 64 * 64;
#pragma unroll
            for (int i = 0; i < 4; i++) {
                cpa16(ksb[buf] + kvswo[i], kp + (size_t)kvrow[i] * 64 + kvg[i] * 8);
                cpa16(vsb[buf] + kvswo[i], vp + (size_t)kvrow[i] * 64 + kvg[i] * 8);
            }
        }
        CPA_COMMIT();
    };

    load_kv(0);
    for (int i = tid; i < 1024; i += 128) {
        int row = i >> 3, g = i & 7;
        *(uint4*)(Qs + row * 128 + ((g ^ (row & 7)) << 4)) =
            *(const uint4*)&qh[(size_t)(q0 + row) * 64 + g * 8];
    }
    __syncthreads();

    uint32_t qf[2][4][4];
#pragma unroll
    for (int mt = 0; mt < 2; mt++) {
        uint32_t rowA = (uint32_t)((w << 5) + (mt << 4) + (lane & 15));
        uint32_t aB = qsb + rowA * 128, aXor = rowA & 7, aG = (uint32_t)(lane >> 4);
#pragma unroll
        for (int dk = 0; dk < 4; dk++)
            ldsm4(qf[mt][dk], aB + ((((uint32_t)(2 * dk) + aG) ^ aXor) << 4));
    }

    float acc_o[2][8][4];
#pragma unroll
    for (int mt = 0; mt < 2; mt++)
#pragma unroll
        for (int i = 0; i < 8; i++)
#pragma unroll
            for (int j = 0; j < 4; j++) acc_o[mt][i][j] = 0.f;
    float rs[2][2] = {{0.f, 0.f}, {0.f, 0.f}};

    uint32_t sRow = (uint32_t)(lane & 7) * 128;
    uint32_t sXor = (uint32_t)(lane & 7), sG = (uint32_t)((lane >> 3) & 1);
    uint32_t vRow = (uint32_t)(lane & 15) * 128;
    uint32_t vXor = (uint32_t)(lane & 7);

    for (int kt = 0; kt < 16; kt++) {
        CPA_WAIT(0);
        __syncthreads();
        load_kv(kt + 1);
        int buf = kt & 1;
        uint32_t sRowB = ksb[buf] + sRow;
        uint32_t vRowB = vsb[buf] + vRow;

        uint32_t pa[2][4][4];
#pragma unroll
        for (int nt = 0; nt < 8; nt++) {
            float s0[4] = {0.f, 0.f, 0.f, 0.f};
            float s1[4] = {0.f, 0.f, 0.f, 0.f};
#pragma unroll
            for (int dk = 0; dk < 4; dk++) {
                uint32_t bf[2];
                ldsm2(bf, sRowB + nt * 1024 + ((((uint32_t)(2 * dk) + sG) ^ sXor) << 4));
                mma16(s0, qf[0][dk], bf);
                mma16(s1, qf[1][dk], bf);
            }
            int kk = nt >> 1, half = (nt & 1) << 1;
            {
                float e0 = exps(s0[0]), e1 = exps(s0[1]);
                float e2 = exps(s0[2]), e3 = exps(s0[3]);
                rs[0][0] += e0 + e1; rs[0][1] += e2 + e3;
                pa[0][kk][half + 0] = packbf(e0, e1);
                pa[0][kk][half + 1] = packbf(e2, e3);
            }
            {
                float e0 = exps(s1[0]), e1 = exps(s1[1]);
                float e2 = exps(s1[2]), e3 = exps(s1[3]);
                rs[1][0] += e0 + e1; rs[1][1] += e2 + e3;
                pa[1][kk][half + 0] = packbf(e0, e1);
                pa[1][kk][half + 1] = packbf(e2, e3);
            }
        }

#pragma unroll
        for (int nt = 0; nt < 8; nt++) {
#pragma unroll
            for (int kk = 0; kk < 4; kk++) {
                uint32_t bf[2];
                ldsm2t(bf, vRowB + kk * 2048 + ((((uint32_t)nt) ^ vXor) << 4));
                mma16(acc_o[0][nt], pa[0][kk], bf);
                mma16(acc_o[1][nt], pa[1][kk], bf);
            }
        }
    }

#pragma unroll
    for (int mt = 0; mt < 2; mt++)
#pragma unroll
        for (int i = 0; i < 2; i++) {
            rs[mt][i] += __shfl_xor_sync(0xffffffffu, rs[mt][i], 1);
            rs[mt][i] += __shfl_xor_sync(0xffffffffu, rs[mt][i], 2);
        }

    int col = (h << 6) + ((lane & 3) << 1);
#pragma unroll
    for (int mt = 0; mt < 2; mt++) {
        int r0 = q0 + (w << 5) + (mt << 4) + (lane >> 2);
        float inv0 = 1.f / rs[mt][0], inv1 = 1.f / rs[mt][1];
#pragma unroll
        for (int nt = 0; nt < 8; nt++) {
            *(uint32_t*)&xattn[(size_t)r0 * 1024 + col + nt * 8] =
                packbf(acc_o[mt][nt][0] * inv0, acc_o[mt][nt][1] * inv0);
            *(uint32_t*)&xattn[(size_t)(r0 + 8) * 1024 + col + nt * 8] =
                packbf(acc_o[mt][nt][2] * inv1, acc_o[mt][nt][3] * inv1);
        }
    }
}

// ---------------- fused: x1 = mp_add(x, pn(t)*e^g); xs = xcond(x1) ----------
__global__ void add_xcond_kernel(const float* __restrict__ base,
                                 const __nv_bfloat16* __restrict__ tin,
                                 const float* __restrict__ gainp,
                                 const float* __restrict__ cc,
                                 float* __restrict__ x1,
                                 __nv_bfloat16* __restrict__ xs) {
    int row = blockIdx.x;
    int b = row >> 10;
    uint2 u = *(const uint2*)&tin[(size_t)row * HID + threadIdx.x * 4];
    float2 t0 = upk(u.x), t1 = upk(u.y);
    float sum = t0.x * t0.x + t0.y * t0.y + t1.x * t1.x + t1.y * t1.y;
    float tot = blockReduceSum(sum);
    float r = rsqrtf(tot * (1.f / 1024.f) + 1e-4f) * expf(gainp[0]);
    float4 bv = ((const float4*)(base + (size_t)row * HID))[threadIdx.x];
    const float mp = 1.0f / sqrtf(0.58f);
    float4 o;
    o.x = (0.7f * bv.x + 0.3f * t0.x * r) * mp;
    o.y = (0.7f * bv.y + 0.3f * t0.y * r) * mp;
    o.z = (0.7f * bv.z + 0.3f * t1.x * r) * mp;
    o.w = (0.7f * bv.w + 0.3f * t1.y * r) * mp;
    ((float4*)(x1 + (size_t)row * HID))[threadIdx.x] = o;
    float sum2 = o.x * o.x + o.y * o.y + o.z * o.z + o.w * o.w;
    float tot2 = blockReduceSum(sum2);
    float r2 = rsqrtf(tot2 * (1.f / 1024.f) + 1e-4f);
    int col = threadIdx.x * 4;
    const float* ccb = cc + b * 2048;
    float ox = o.x * r2 * (1.f + ccb[col + 0]) + ccb[1024 + col + 0];
    float oy = o.y * r2 * (1.f + ccb[col + 1]) + ccb[1024 + col + 1];
    float oz = o.z * r2 * (1.f + ccb[col + 2]) + ccb[1024 + col + 2];
    float ow = o.w * r2 * (1.f + ccb[col + 3]) + ccb[1024 + col + 3];
    *(uint2*)&xs[(size_t)row * HID + col] = make_uint2(packbf(ox, oy), packbf(oz, ow));
}

// ---------------- epilogue: out = mp_add(base, pixel_norm(t)*exp(g)) ---------
__global__ void add_epilogue_kernel(const float* __restrict__ base,
                                    const __nv_bfloat16* __restrict__ tin,
                                    const float* __restrict__ gainp,
                                    float* __restrict__ outp) {
    int row = blockIdx.x;
    uint2 u = *(const uint2*)&tin[(size_t)row * HID + threadIdx.x * 4];
    float2 t0 = upk(u.x), t1 = upk(u.y);
    float sum = t0.x * t0.x + t0.y * t0.y + t1.x * t1.x + t1.y * t1.y;
    float tot = blockReduceSum(sum);
    float r = rsqrtf(tot * (1.f / 1024.f) + 1e-4f) * expf(gainp[0]);
    float4 bv = ((const float4*)(base + (size_t)row * HID))[threadIdx.x];
    const float mp = 1.0f / sqrtf(0.58f);
    float4 o;
    o.x = (0.7f * bv.x + 0.3f * t0.x * r) * mp;
    o.y = (0.7f * bv.y + 0.3f * t0.y * r) * mp;
    o.z = (0.7f * bv.z + 0.3f * t1.x * r) * mp;
    o.w = (0.7f * bv.w + 0.3f * t1.y * r) * mp;
    ((float4*)(outp + (size_t)row * HID))[threadIdx.x] = o;
}

// ---------------- h post: mp_silu(pixel_norm(h)) (in place, bf16) ------------
__global__ void hpost_kernel(__nv_bfloat16* __restrict__ hbuf) {
    int row = blockIdx.x;
    uint2* p = (uint2*)(hbuf + (size_t)row * MLPD);
    float2 vv[4][2];
    float sum = 0.f;
#pragma unroll
    for (int i = 0; i < 4; i++) {
        uint2 u = p[threadIdx.x + i * 256];
        vv[i][0] = upk(u.x);
        vv[i][1] = upk(u.y);
        sum += vv[i][0].x * vv[i][0].x + vv[i][0].y * vv[i][0].y
             + vv[i][1].x * vv[i][1].x + vv[i][1].y * vv[i][1].y;
    }
    float tot = blockReduceSum(sum);
    float r = rsqrtf(tot * (1.f / 4096.f) + 1e-4f);
#pragma unroll
    for (int i = 0; i < 4; i++) {
        float u0, u1, u2, u3;
        u0 = vv[i][0].x * r; u0 = u0 / (1.f + __expf(-u0)) * (1.0f / 0.596f);
        u1 = vv[i][0].y * r; u1 = u1 / (1.f + __expf(-u1)) * (1.0f / 0.596f);
        u2 = vv[i][1].x * r; u2 = u2 / (1.f + __expf(-u2)) * (1.0f / 0.596f);
        u3 = vv[i][1].y * r; u3 = u3 / (1.f + __expf(-u3)) * (1.0f / 0.596f);
        p[threadIdx.x + i * 256] = make_uint2(packbf(u0, u1), packbf(u2, u3));
    }
}

// ---------------- launch ------------------------------------------------------
extern "C" void kernel_launch(void* const* d_in, const int* in_sizes, int n_in,
                              void* d_out, int out_size) {
    const float* x      = (const float*)d_in[0];
    const float* c      = (const float*)d_in[1];
    const float* w_cond = (const float*)d_in[2];
    const float* w_qkv  = (const float*)d_in[3];
    const float* w_out  = (const float*)d_in[4];
    const float* w_mlp1 = (const float*)d_in[5];
    const float* w_mlp2 = (const float*)d_in[6];
    const float* attn_g = (const float*)d_in[7];
    const float* mlp_g  = (const float*)d_in[8];
    float* out          = (float*)d_out;

    float *s_cond, *s_qkv, *s_out_, *s_mlp1, *s_mlp2;
    float *ccp, *cc, *x1;
    __nv_bfloat16 *xs, *big, *q, *k, *v, *xattn, *t1;
    __nv_bfloat16 *wt_qkv, *wt_out, *wt_mlp1, *wt_mlp2;
    cudaGetSymbolAddress((void**)&s_cond, g_s_cond);
    cudaGetSymbolAddress((void**)&s_qkv, g_s_qkv);
    cudaGetSymbolAddress((void**)&s_out_, g_s_out);
    cudaGetSymbolAddress((void**)&s_mlp1, g_s_mlp1);
    cudaGetSymbolAddress((void**)&s_mlp2, g_s_mlp2);
    cudaGetSymbolAddress((void**)&ccp, g_ccp);
    cudaGetSymbolAddress((void**)&cc, g_cc);
    cudaGetSymbolAddress((void**)&xs, g_xs);
    cudaGetSymbolAddress((void**)&big, g_big);
    cudaGetSymbolAddress((void**)&q, g_q);
    cudaGetSymbolAddress((void**)&k, g_k);
    cudaGetSymbolAddress((void**)&v, g_v);
    cudaGetSymbolAddress((void**)&xattn, g_xattn);
    cudaGetSymbolAddress((void**)&t1, g_t1);
    cudaGetSymbolAddress((void**)&x1, g_x1);
    cudaGetSymbolAddress((void**)&wt_qkv, g_wt_qkv);
    cudaGetSymbolAddress((void**)&wt_out, g_wt_out);
    cudaGetSymbolAddress((void**)&wt_mlp1, g_wt_mlp1);
    cudaGetSymbolAddress((void**)&wt_mlp2, g_wt_mlp2);

    static int configured = 0;
    if (!configured) {
        cudaFuncSetAttribute(gemm_mma_kernel,
                             cudaFuncAttributeMaxDynamicSharedMemorySize, GEMM_SMEM);
        configured = 1;
    }

    // prep: row-norm scales, then fused transpose/scale-fold/bf16
    rownorm_all_kernel<<<1024, 256>>>(w_cond, w_qkv, w_out, w_mlp1, w_mlp2,
                                      s_cond, s_qkv, s_out_, s_mlp1, s_mlp2);
    transpose_all_kernel<<<12288, dim3(32, 8)>>>(
        w_qkv, w_out, w_mlp1, w_mlp2, s_qkv, s_out_, s_mlp1, s_mlp2,
        wt_qkv, wt_out, wt_mlp1, wt_mlp2);

    // conditioning -> gain/shift
    cond_gemm_part_kernel<<<dim3(8, 32), 256>>>(c, s_cond, w_cond, ccp);
    cond_reduce_kernel<<<32, 256>>>(ccp, cc);

    // attention branch (GEMM grids now (N/128, M/256))
    xcond_kernel<<<RWS, 256>>>(x, cc, xs);
    gemm_mma_kernel<<<dim3(24, 16), 256, GEMM_SMEM>>>(xs, wt_qkv, big, 1024, 3072);
    qkv_post_kernel<<<dim3(RWS, 3), 256>>>(big, q, k, v);
    attn_mma_kernel<<<dim3(8, 64), 128>>>(q, k, v, xattn);
    gemm_mma_kernel<<<dim3(8, 16), 256, GEMM_SMEM>>>(xattn, wt_out, t1, 1024, 1024);
    add_xcond_kernel<<<RWS, 256>>>(x, t1, attn_g, cc, x1, xs);

    // MLP branch
    gemm_mma_kernel<<<dim3(32, 16), 256, GEMM_SMEM>>>(xs, wt_mlp1, big, 1024, 4096);
    hpost_kernel<<<RWS, 256>>>(big);
    gemm_mma_kernel<<<dim3(8, 16), 256, GEMM_SMEM>>>(big, wt_mlp2, t1, 4096, 1024);
    add_epilogue_kernel<<<RWS, 256>>>(x1, t1, mlp_g, out);
}